// round 2
// baseline (speedup 1.0000x reference)
#include <cuda_runtime.h>
#include <math.h>

// Problem constants
#define Bb 4
#define Ss 20
#define IMm 64
#define Dd 8
#define NLl 4
#define NPOS (Bb*Ss*IMm*IMm)
#define NELEM (NPOS*Dd)
#define LOG2E 1.4426950408889634f

// Scratch (no allocations allowed)
__device__ float g_xt[NELEM];
__device__ float g_bufA[NELEM];
__device__ float g_bufB[NELEM];
__device__ float g_logits[Bb];

// ---------------- packed f32x2 helpers (sm_103a) ----------------
typedef unsigned long long u64t;
__device__ __forceinline__ u64t pk2(float lo, float hi) {
    u64t r; asm("mov.b64 %0, {%1,%2};" : "=l"(r) : "f"(lo), "f"(hi)); return r;
}
__device__ __forceinline__ void up2(u64t v, float& a, float& b) {
    asm("mov.b64 {%0,%1}, %2;" : "=f"(a), "=f"(b) : "l"(v));
}
__device__ __forceinline__ u64t fma2(u64t a, u64t b, u64t c) {
    u64t d; asm("fma.rn.f32x2 %0, %1, %2, %3;" : "=l"(d) : "l"(a), "l"(b), "l"(c)); return d;
}
__device__ __forceinline__ u64t mul2(u64t a, u64t b) {
    u64t d; asm("mul.rn.f32x2 %0, %1, %2;" : "=l"(d) : "l"(a), "l"(b)); return d;
}
__device__ __forceinline__ u64t add2(u64t a, u64t b) {
    u64t d; asm("add.rn.f32x2 %0, %1, %2;" : "=l"(d) : "l"(a), "l"(b)); return d;
}
__device__ __forceinline__ float ex2f(float x) {
    float r; asm("ex2.approx.f32 %0, %1;" : "=f"(r) : "f"(x)); return r;
}

// ---------------------------------------------------------------------------
// Embed
// ---------------------------------------------------------------------------
__global__ void embed_kernel(const float* __restrict__ x,
                             const float* __restrict__ conv_w,
                             const float* __restrict__ pos_s,
                             const float* __restrict__ pos_h,
                             const float* __restrict__ pos_w)
{
    int idx = blockIdx.x * blockDim.x + threadIdx.x;
    if (idx < Bb) g_logits[idx] = 0.0f;
    if (idx >= NPOS) return;
    int w = idx & 63;
    int t = idx >> 6;
    int h = t & 63;
    t >>= 6;
    int s = t % Ss;
    float xv = x[idx];
    float vals[8];
#pragma unroll
    for (int d = 0; d < 8; d++) {
        float v = fmaxf(xv * conv_w[d], 0.0f);
        v += pos_s[s * 8 + d] + pos_h[d * 64 + h] + pos_w[d * 64 + w];
        vals[d] = v;
    }
    float4* o = (float4*)(g_xt + (long)idx * 8);
    o[0] = make_float4(vals[0], vals[1], vals[2], vals[3]);
    o[1] = make_float4(vals[4], vals[5], vals[6], vals[7]);
}

// ---------------------------------------------------------------------------
// Axial attention, L=64 rows. One thread per row. 2-pass softmax (recompute
// dots), packed f32x2 inner loops, K/V in shared laid out [h][e][j].
// ---------------------------------------------------------------------------
template<int NS>
__global__ void __launch_bounds__(64*NS, 8)
axial_attn64(const float* __restrict__ zin, float* __restrict__ zout,
             const float* __restrict__ Wq, const float* __restrict__ Wkv,
             const float* __restrict__ Wo, const float* __restrict__ bo,
             int inner_count, int outer_mult, int stride, int accum)
{
    __shared__ float sWq[128];
    __shared__ float sWkv[256];
    __shared__ float sWo[128];
    __shared__ float sbo[8];
    __shared__ float sK[NS][4][4][64];   // [slot][h][e][j]
    __shared__ float sV[NS][4][4][64];

    const int i   = threadIdx.x;      // row 0..63
    const int sl  = threadIdx.y;
    const int tid = sl * 64 + i;
    const int nth = 64 * NS;

    for (int t = tid; t < 128; t += nth) sWq[t]  = Wq[t];
    for (int t = tid; t < 256; t += nth) sWkv[t] = Wkv[t];
    for (int t = tid; t < 128; t += nth) sWo[t]  = Wo[t];
    if (tid < 8) sbo[tid] = bo[tid];

    const int seq   = blockIdx.x * NS + sl;
    const int outer = seq / inner_count;
    const int rem   = seq - outer * inner_count;
    const long base = (long)outer * outer_mult + rem;

    const float* zr = zin + (base + (long)i * stride) * 8;
    float4 a0 = *(const float4*)zr;
    float4 a1 = *(const float4*)(zr + 4);
    float row[8] = {a0.x, a0.y, a0.z, a0.w, a1.x, a1.y, a1.z, a1.w};

    __syncthreads();  // weights ready

    // k,v projections -> shared [h][e][j]
#pragma unroll
    for (int h = 0; h < 4; h++) {
#pragma unroll
        for (int e = 0; e < 4; e++) {
            float sk = 0.0f, sv = 0.0f;
#pragma unroll
            for (int d = 0; d < 8; d++) {
                sk = fmaf(row[d], sWkv[d * 32 + h * 4 + e], sk);
                sv = fmaf(row[d], sWkv[d * 32 + 16 + h * 4 + e], sv);
            }
            sK[sl][h][e][i] = sk;
            sV[sl][h][e][i] = sv;
        }
    }
    __syncthreads();

    float outv[8];
#pragma unroll
    for (int d = 0; d < 8; d++) outv[d] = sbo[d];

#pragma unroll 1
    for (int h = 0; h < 4; h++) {
        // q for this head, pre-scaled by 0.5 * log2(e), packed (q,q)
        u64t qp[4];
#pragma unroll
        for (int e = 0; e < 4; e++) {
            float s = 0.0f;
#pragma unroll
            for (int d = 0; d < 8; d++) s = fmaf(row[d], sWq[d * 16 + h * 4 + e], s);
            s *= 0.5f * LOG2E;
            qp[e] = pk2(s, s);
        }
        const ulonglong2* K0 = (const ulonglong2*)sK[sl][h][0];
        const ulonglong2* K1 = (const ulonglong2*)sK[sl][h][1];
        const ulonglong2* K2 = (const ulonglong2*)sK[sl][h][2];
        const ulonglong2* K3 = (const ulonglong2*)sK[sl][h][3];
        const ulonglong2* V0 = (const ulonglong2*)sV[sl][h][0];
        const ulonglong2* V1 = (const ulonglong2*)sV[sl][h][1];
        const ulonglong2* V2 = (const ulonglong2*)sV[sl][h][2];
        const ulonglong2* V3 = (const ulonglong2*)sV[sl][h][3];

        // pass 1: max of (log2-scaled) dots
        float m = -1e30f;
#pragma unroll 4
        for (int jg = 0; jg < 16; jg++) {
            ulonglong2 k0 = K0[jg], k1 = K1[jg], k2 = K2[jg], k3 = K3[jg];
            u64t d01 = mul2(qp[0], k0.x);
            d01 = fma2(qp[1], k1.x, d01);
            d01 = fma2(qp[2], k2.x, d01);
            d01 = fma2(qp[3], k3.x, d01);
            u64t d23 = mul2(qp[0], k0.y);
            d23 = fma2(qp[1], k1.y, d23);
            d23 = fma2(qp[2], k2.y, d23);
            d23 = fma2(qp[3], k3.y, d23);
            float x0, x1, x2, x3;
            up2(d01, x0, x1);
            up2(d23, x2, x3);
            m = fmaxf(m, fmaxf(fmaxf(x0, x1), fmaxf(x2, x3)));
        }

        // pass 2: recompute dots with -m folded into accumulator init; exp2;
        // packed sum + packed o accumulation
        u64t mneg = pk2(-m, -m);
        u64t s01 = pk2(0.0f, 0.0f);
        u64t o0 = s01, o1 = s01, o2 = s01, o3 = s01;
#pragma unroll 4
        for (int jg = 0; jg < 16; jg++) {
            ulonglong2 k0 = K0[jg], k1 = K1[jg], k2 = K2[jg], k3 = K3[jg];
            u64t d01 = fma2(qp[0], k0.x, mneg);
            d01 = fma2(qp[1], k1.x, d01);
            d01 = fma2(qp[2], k2.x, d01);
            d01 = fma2(qp[3], k3.x, d01);
            u64t d23 = fma2(qp[0], k0.y, mneg);
            d23 = fma2(qp[1], k1.y, d23);
            d23 = fma2(qp[2], k2.y, d23);
            d23 = fma2(qp[3], k3.y, d23);
            float x0, x1, x2, x3;
            up2(d01, x0, x1);
            up2(d23, x2, x3);
            float e0 = ex2f(x0), e1 = ex2f(x1), e2 = ex2f(x2), e3 = ex2f(x3);
            u64t e01 = pk2(e0, e1);
            u64t e23 = pk2(e2, e3);
            s01 = add2(s01, e01);
            s01 = add2(s01, e23);
            ulonglong2 v0 = V0[jg], v1 = V1[jg], v2 = V2[jg], v3 = V3[jg];
            o0 = fma2(e01, v0.x, o0); o0 = fma2(e23, v0.y, o0);
            o1 = fma2(e01, v1.x, o1); o1 = fma2(e23, v1.y, o1);
            o2 = fma2(e01, v2.x, o2); o2 = fma2(e23, v2.y, o2);
            o3 = fma2(e01, v3.x, o3); o3 = fma2(e23, v3.y, o3);
        }
        float sa, sb;
        up2(s01, sa, sb);
        float inv = 1.0f / (sa + sb);
        float oe[4];
        {
            float ua, ub;
            up2(o0, ua, ub); oe[0] = (ua + ub) * inv;
            up2(o1, ua, ub); oe[1] = (ua + ub) * inv;
            up2(o2, ua, ub); oe[2] = (ua + ub) * inv;
            up2(o3, ua, ub); oe[3] = (ua + ub) * inv;
        }
        // accumulate into output projection
#pragma unroll
        for (int e = 0; e < 4; e++) {
#pragma unroll
            for (int d = 0; d < 8; d++)
                outv[d] = fmaf(oe[e], sWo[(h * 4 + e) * 8 + d], outv[d]);
        }
    }

    float* zo = zout + (base + (long)i * stride) * 8;
    if (accum) {
        float4 o0r = *(float4*)zo;
        float4 o1r = *(float4*)(zo + 4);
        outv[0] += o0r.x; outv[1] += o0r.y; outv[2] += o0r.z; outv[3] += o0r.w;
        outv[4] += o1r.x; outv[5] += o1r.y; outv[6] += o1r.z; outv[7] += o1r.w;
    }
    ((float4*)zo)[0] = make_float4(outv[0], outv[1], outv[2], outv[3]);
    ((float4*)zo)[1] = make_float4(outv[4], outv[5], outv[6], outv[7]);
}

// ---------------------------------------------------------------------------
// Axial attention, L=20 (sequence axis). Registers fine -> keep p[20].
// ---------------------------------------------------------------------------
template<int L, int NS>
__global__ void __launch_bounds__(L*NS)
axial_attn(const float* __restrict__ zin, float* __restrict__ zout,
           const float* __restrict__ Wq, const float* __restrict__ Wkv,
           const float* __restrict__ Wo, const float* __restrict__ bo,
           int inner_count, int outer_mult, int stride, int accum)
{
    __shared__ float sWq[128];
    __shared__ float sWkv[256];
    __shared__ float sWo[128];
    __shared__ float sbo[8];
    __shared__ float4 sKq[NS][4][L];
    __shared__ float4 sVq[NS][4][L];

    const int i   = threadIdx.x;
    const int sl  = threadIdx.y;
    const int tid = sl * L + i;
    const int nth = L * NS;

    for (int t = tid; t < 128; t += nth) sWq[t]  = Wq[t];
    for (int t = tid; t < 256; t += nth) sWkv[t] = Wkv[t];
    for (int t = tid; t < 128; t += nth) sWo[t]  = Wo[t];
    if (tid < 8) sbo[tid] = bo[tid];

    const int seq   = blockIdx.x * NS + sl;
    const int outer = seq / inner_count;
    const int rem   = seq - outer * inner_count;
    const long base = (long)outer * outer_mult + rem;

    const float* zr = zin + (base + (long)i * stride) * 8;
    float4 a0 = *(const float4*)zr;
    float4 a1 = *(const float4*)(zr + 4);
    float row[8] = {a0.x, a0.y, a0.z, a0.w, a1.x, a1.y, a1.z, a1.w};

    __syncthreads();

    float q[16];
#pragma unroll
    for (int c = 0; c < 16; c++) {
        float s = 0.0f;
#pragma unroll
        for (int d = 0; d < 8; d++) s = fmaf(row[d], sWq[d * 16 + c], s);
        q[c] = s * (0.5f * LOG2E);
    }
#pragma unroll
    for (int h = 0; h < 4; h++) {
        float4 kk, vv;
        float* kp = (float*)&kk;
        float* vp = (float*)&vv;
#pragma unroll
        for (int e = 0; e < 4; e++) {
            float sk = 0.0f, sv = 0.0f;
#pragma unroll
            for (int d = 0; d < 8; d++) {
                sk = fmaf(row[d], sWkv[d * 32 + h * 4 + e], sk);
                sv = fmaf(row[d], sWkv[d * 32 + 16 + h * 4 + e], sv);
            }
            kp[e] = sk; vp[e] = sv;
        }
        sKq[sl][h][i] = kk;
        sVq[sl][h][i] = vv;
    }
    __syncthreads();

    float oacc[16];
#pragma unroll
    for (int h = 0; h < 4; h++) {
        const float qx = q[h*4+0], qy = q[h*4+1], qz = q[h*4+2], qw = q[h*4+3];
        float p[L];
        float m = -1e30f;
#pragma unroll
        for (int j = 0; j < L; j++) {
            float4 kj = sKq[sl][h][j];
            float d = qx*kj.x + qy*kj.y + qz*kj.z + qw*kj.w;
            p[j] = d;
            m = fmaxf(m, d);
        }
        float ssum = 0.0f;
        float ox = 0.f, oy = 0.f, oz = 0.f, ow = 0.f;
#pragma unroll
        for (int j = 0; j < L; j++) {
            float e = ex2f(p[j] - m);
            ssum += e;
            float4 vj = sVq[sl][h][j];
            ox = fmaf(e, vj.x, ox);
            oy = fmaf(e, vj.y, oy);
            oz = fmaf(e, vj.z, oz);
            ow = fmaf(e, vj.w, ow);
        }
        float inv = 1.0f / ssum;
        oacc[h*4+0] = ox * inv;
        oacc[h*4+1] = oy * inv;
        oacc[h*4+2] = oz * inv;
        oacc[h*4+3] = ow * inv;
    }

    float outv[8];
#pragma unroll
    for (int d = 0; d < 8; d++) {
        float s = sbo[d];
#pragma unroll
        for (int c = 0; c < 16; c++) s = fmaf(oacc[c], sWo[c * 8 + d], s);
        outv[d] = s;
    }

    float* zo = zout + (base + (long)i * stride) * 8;
    if (accum) {
        float4 o0 = *(float4*)zo;
        float4 o1 = *(float4*)(zo + 4);
        outv[0] += o0.x; outv[1] += o0.y; outv[2] += o0.z; outv[3] += o0.w;
        outv[4] += o1.x; outv[5] += o1.y; outv[6] += o1.z; outv[7] += o1.w;
    }
    ((float4*)zo)[0] = make_float4(outv[0], outv[1], outv[2], outv[3]);
    ((float4*)zo)[1] = make_float4(outv[4], outv[5], outv[6], outv[7]);
}

// ---------------------------------------------------------------------------
// Epilogue
// ---------------------------------------------------------------------------
__global__ void reduce_kernel(const float* __restrict__ zfin,
                              const float* __restrict__ Wc)
{
    const int b = blockIdx.y;
    const int t = blockIdx.x * blockDim.x + threadIdx.x;
    const int d  = t & 7;
    const int hw = t >> 3;
    long base = (long)b * Ss * 32768 + (long)hw * 8 + d;
    float m = -1e30f;
#pragma unroll
    for (int s = 0; s < Ss; s++) {
        long o = base + (long)s * 32768;
        m = fmaxf(m, zfin[o] + g_xt[o]);
    }
    float val = m * Wc[d * 4096 + hw];

    __shared__ float red[256];
    red[threadIdx.x] = val;
    __syncthreads();
    for (int off = 128; off > 0; off >>= 1) {
        if (threadIdx.x < off) red[threadIdx.x] += red[threadIdx.x + off];
        __syncthreads();
    }
    if (threadIdx.x == 0) atomicAdd(&g_logits[b], red[0]);
}

__global__ void final_kernel(const float* __restrict__ bc, float* __restrict__ out)
{
    int b = threadIdx.x;
    if (b < Bb) {
        float lg = g_logits[b] + bc[0];
        out[b] = 1.0f / (1.0f + __expf(-lg));
    }
}

// ---------------------------------------------------------------------------
extern "C" void kernel_launch(void* const* d_in, const int* in_sizes, int n_in,
                              void* d_out, int out_size)
{
    const float* x      = (const float*)d_in[0];
    const float* conv_w = (const float*)d_in[1];
    const float* pos_s  = (const float*)d_in[2];
    const float* pos_h  = (const float*)d_in[3];
    const float* pos_w  = (const float*)d_in[4];
    const float* Wq     = (const float*)d_in[5];
    const float* Wkv    = (const float*)d_in[6];
    const float* Wo     = (const float*)d_in[7];
    const float* bo     = (const float*)d_in[8];
    const float* Wc     = (const float*)d_in[9];
    const float* bc     = (const float*)d_in[10];
    float* out = (float*)d_out;

    float *pXt = nullptr, *pA = nullptr, *pB = nullptr;
    cudaGetSymbolAddress((void**)&pXt, g_xt);
    cudaGetSymbolAddress((void**)&pA,  g_bufA);
    cudaGetSymbolAddress((void**)&pB,  g_bufB);

    embed_kernel<<<(NPOS + 255) / 256, 256>>>(x, conv_w, pos_s, pos_h, pos_w);

    float* cur = pXt;
    for (int l = 0; l < NLl; l++) {
        float* nxt = (l & 1) ? pB : pA;
        const float* wq0 = Wq  + (l * 3 + 0) * 128;
        const float* wk0 = Wkv + (l * 3 + 0) * 256;
        const float* wo0 = Wo  + (l * 3 + 0) * 128;
        const float* bo0 = bo  + (l * 3 + 0) * 8;

        // axis 1 (S, L=20): write
        {
            dim3 blk(20, 8);
            axial_attn<20, 8><<<Bb * IMm * IMm / 8, blk>>>(
                cur, nxt, wq0, wk0, wo0, bo0,
                IMm * IMm, Ss * IMm * IMm, IMm * IMm, 0);
        }
        // axis 2 (H, L=64): accumulate
        {
            dim3 blk(64, 2);
            axial_attn64<2><<<Bb * Ss * IMm / 2, blk>>>(
                cur, nxt, wq0 + 128, wk0 + 256, wo0 + 128, bo0 + 8,
                IMm, IMm * IMm, IMm, 1);
        }
        // axis 3 (W, L=64): accumulate
        {
            dim3 blk(64, 2);
            axial_attn64<2><<<Bb * Ss * IMm / 2, blk>>>(
                cur, nxt, wq0 + 256, wk0 + 512, wo0 + 256, bo0 + 16,
                1, IMm, 1, 1);
        }
        cur = nxt;
    }

    {
        dim3 grid(IMm * IMm * Dd / 256, Bb);
        reduce_kernel<<<grid, 256>>>(cur, Wc);
    }
    final_kernel<<<1, 32>>>(bc, out);
}